// round 14
// baseline (speedup 1.0000x reference)
#include <cuda_runtime.h>
#include <cuda_fp16.h>
#include <cstdint>

#define NN      100000
#define TT      4
#define EE      400000
#define TE      1600000
#define CC      2
#define LL      2
#define WIN     128
#define DD      64
#define CD      128
#define NCLS    16
#define MM      10000

// ---------------- device scratch (static; no runtime allocation) ------------
__device__ __half   g_Xh[NN * CD];      // fp16 projected input (SpMM l0 in + tail mix)
__device__ __half   g_H0[NN * CD];      // fp16 layer-0 output
__device__ __half   g_H1[NN * CD];      // fp16 layer-1 output
__device__ uint2    g_ed[TE];           // packed edge: {col | type<<20, w bits}
__device__ int      g_cnt[NN];
__device__ int      g_off[NN + 1];
__device__ int      g_cur[NN];
__device__ int      g_bsum[256];
__device__ float    g_filt[LL * CC * TT];

__device__ __forceinline__ unsigned tf32cvt(float x) {
    unsigned r;
    asm("cvt.rna.tf32.f32 %0, %1;" : "=r"(r) : "f"(x));
    return r;
}

// ---------------- zero counters + softmax over edge types (fused) -----------
__global__ void k_zero(const float* __restrict__ cw) {
    int i = blockIdx.x * blockDim.x + threadIdx.x;
    if (i < NN) g_cnt[i] = 0;
    if (blockIdx.x == 0 && threadIdx.x < LL * CC) {
        const float* p = cw + threadIdx.x * TT;
        float m = p[0];
        for (int t = 1; t < TT; t++) m = fmaxf(m, p[t]);
        float e[TT]; float s = 0.f;
        for (int t = 0; t < TT; t++) { e[t] = __expf(p[t] - m); s += e[t]; }
        float inv = 1.f / s;
        for (int t = 0; t < TT; t++) g_filt[threadIdx.x * TT + t] = e[t] * inv;
    }
}

__global__ void k_hist(const int* __restrict__ ei) {
    int idx = blockIdx.x * blockDim.x + threadIdx.x;
    if (idx >= TE) return;
    int t = idx / EE;
    int e = idx - t * EE;
    int dst = ei[t * 2 * EE + e];
    atomicAdd(&g_cnt[dst], 1);
}

#define SCHUNK 512
#define SNB    196            // ceil(100000/512)

__global__ void k_scan1() {
    __shared__ int s[SCHUNK];
    int tid = threadIdx.x;
    int i = blockIdx.x * SCHUNK + tid;
    int v = (i < NN) ? g_cnt[i] : 0;
    s[tid] = v;
    __syncthreads();
    for (int o = 1; o < SCHUNK; o <<= 1) {
        int t = (tid >= o) ? s[tid - o] : 0;
        __syncthreads();
        s[tid] += t;
        __syncthreads();
    }
    if (i < NN) g_off[i] = s[tid] - v;
    if (tid == SCHUNK - 1) g_bsum[blockIdx.x] = s[tid];
}

// fused: every block redundantly scans the 196 block sums, then applies base
__global__ void k_scan23() {
    __shared__ int s[256];
    int tid = threadIdx.x;
    if (tid < 256) s[tid] = (tid < SNB) ? g_bsum[tid] : 0;
    __syncthreads();
    for (int o = 1; o < 256; o <<= 1) {
        int t = 0;
        if (tid < 256 && tid >= o) t = s[tid - o];
        __syncthreads();
        if (tid < 256) s[tid] += t;
        __syncthreads();
    }
    int base = (blockIdx.x > 0) ? s[blockIdx.x - 1] : 0;
    int i = blockIdx.x * SCHUNK + tid;
    if (i < NN) {
        int o = g_off[i] + base;
        g_off[i] = o;
        g_cur[i] = o;
    }
    if (blockIdx.x == 0 && tid == 0) g_off[NN] = TE;
}

__global__ void k_scatter(const int* __restrict__ ei, const float* __restrict__ ev) {
    int idx = blockIdx.x * blockDim.x + threadIdx.x;
    if (idx >= TE) return;
    int t = idx / EE;
    int e = idx - t * EE;
    int dst = ei[t * 2 * EE + e];
    int col = ei[t * 2 * EE + EE + e];
    int pos = atomicAdd(&g_cur[dst], 1);
    uint2 rec;
    rec.x = (unsigned)col | ((unsigned)t << 20);
    rec.y = __float_as_uint(ev[idx]);
    g_ed[pos] = rec;
}

// ---------------- input projection: tf32 mma.sync (R13, measured 37us) ------
#define RT   64               // rows per block
#define KC   32               // k-chunk
#define XP   36               // padded k stride (bank-conflict-free fragments)

__global__ void __launch_bounds__(256) k_gemm(const float* __restrict__ X,
                                              const float* __restrict__ Ws) {
    __shared__ unsigned Xs[RT][XP];     // [row][k] tf32 bits
    __shared__ unsigned Wsm[CD][XP];    // [n][k] tf32 bits
    int tid  = threadIdx.x;
    int lane = tid & 31;
    int warp = tid >> 5;
    int mg   = warp >> 2;               // m-group 0..1
    int ng   = warp & 3;                // n-group 0..3
    int n0   = blockIdx.x * RT;
    int g  = lane >> 2;                 // group id 0..7
    int tg = lane & 3;                  // thread-in-group 0..3

    float acc[2][4][4];                 // [mtile][ntile][c0..c3]
#pragma unroll
    for (int mt = 0; mt < 2; mt++)
#pragma unroll
        for (int nt = 0; nt < 4; nt++)
#pragma unroll
            for (int r = 0; r < 4; r++) acc[mt][nt][r] = 0.f;

    for (int k0 = 0; k0 < WIN; k0 += KC) {
        // stage X chunk [RT x KC] (512 float4, 256 threads -> 2 each)
#pragma unroll
        for (int idx = tid; idx < RT * (KC / 4); idx += 256) {
            int row = idx >> 3;          // 8 float4 per row
            int c4  = (idx & 7) * 4;
            float4 v = make_float4(0.f, 0.f, 0.f, 0.f);
            if (n0 + row < NN)
                v = *(const float4*)&X[(size_t)(n0 + row) * WIN + k0 + c4];
            Xs[row][c4 + 0] = tf32cvt(v.x);
            Xs[row][c4 + 1] = tf32cvt(v.y);
            Xs[row][c4 + 2] = tf32cvt(v.z);
            Xs[row][c4 + 3] = tf32cvt(v.w);
        }
        // stage W chunk: thread handles n = tid&127, k half kh = tid>>7
        {
            int n  = tid & 127;
            int kh = tid >> 7;           // 0 or 1
            int c = n >> 6, d = n & 63;
            const float* wp = Ws + (size_t)c * WIN * DD
                                 + (size_t)(k0 + kh * 16) * DD + d;
#pragma unroll
            for (int k = 0; k < 16; k++)
                Wsm[n][kh * 16 + k] = tf32cvt(wp[(size_t)k * DD]);
        }
        __syncthreads();

#pragma unroll
        for (int ks = 0; ks < KC / 8; ks++) {
            int kb = ks * 8;
            unsigned a[2][4];
#pragma unroll
            for (int mt = 0; mt < 2; mt++) {
                int r = mg * 32 + mt * 16;
                a[mt][0] = Xs[r + g][kb + tg];
                a[mt][1] = Xs[r + g + 8][kb + tg];
                a[mt][2] = Xs[r + g][kb + tg + 4];
                a[mt][3] = Xs[r + g + 8][kb + tg + 4];
            }
#pragma unroll
            for (int nt = 0; nt < 4; nt++) {
                int n = ng * 32 + nt * 8 + g;
                unsigned b0 = Wsm[n][kb + tg];
                unsigned b1 = Wsm[n][kb + tg + 4];
#pragma unroll
                for (int mt = 0; mt < 2; mt++) {
                    asm volatile(
                        "mma.sync.aligned.m16n8k8.row.col.f32.tf32.tf32.f32 "
                        "{%0,%1,%2,%3}, {%4,%5,%6,%7}, {%8,%9}, {%0,%1,%2,%3};\n"
                        : "+f"(acc[mt][nt][0]), "+f"(acc[mt][nt][1]),
                          "+f"(acc[mt][nt][2]), "+f"(acc[mt][nt][3])
                        : "r"(a[mt][0]), "r"(a[mt][1]), "r"(a[mt][2]), "r"(a[mt][3]),
                          "r"(b0), "r"(b1));
                }
            }
        }
        __syncthreads();
    }

    // epilogue: fp16 only
#pragma unroll
    for (int mt = 0; mt < 2; mt++) {
        int r0 = n0 + mg * 32 + mt * 16 + g;
        int r1 = r0 + 8;
#pragma unroll
        for (int nt = 0; nt < 4; nt++) {
            int col = ng * 32 + nt * 8 + 2 * tg;
            if (r0 < NN)
                *(__half2*)&g_Xh[(size_t)r0 * CD + col] =
                    __floats2half2_rn(acc[mt][nt][0], acc[mt][nt][1]);
            if (r1 < NN)
                *(__half2*)&g_Xh[(size_t)r1 * CD + col] =
                    __floats2half2_rn(acc[mt][nt][2], acc[mt][nt][3]);
        }
    }
}

// ---------------- SpMM: warp per destination, software-pipelined edges ------
__device__ __forceinline__ void gfma(const __half* __restrict__ Hin, unsigned pc,
                                     float f, int off4,
                                     float& ax, float& ay, float& az, float& aw) {
    const uint2 hv = *(const uint2*)(Hin + (size_t)(pc & 0xFFFFFu) * CD + off4);
    float2 p0 = __half22float2(*(const __half2*)&hv.x);
    float2 p1 = __half22float2(*(const __half2*)&hv.y);
    ax += f * p0.x; ay += f * p0.y; az += f * p1.x; aw += f * p1.y;
}

__global__ void __launch_bounds__(256) k_spmm(int layer) {
    const __half* __restrict__ Hin  = (layer == 0) ? g_Xh : g_H0;
    __half* __restrict__       Hout = (layer == 0) ? g_H0 : g_H1;

    __shared__ float fs[CC * TT];
    int tid = threadIdx.x;
    if (tid < CC * TT) fs[tid] = g_filt[layer * CC * TT + tid];
    __syncthreads();

    int wid = (blockIdx.x * blockDim.x + tid) >> 5;
    if (wid >= NN) return;
    int lane = tid & 31;
    int c = lane >> 4;
    const float* fc = fs + c * TT;
    int off4 = lane * 4;

    int i   = g_off[wid];
    int end = g_off[wid + 1];
    float ax = 0.f, ay = 0.f, az = 0.f, aw = 0.f;

    // software pipeline: batch k+1's edge records load before batch k's gathers
    uint2 c0, c1, c2, c3;
    if (i + 4 <= end) {
        c0 = g_ed[i]; c1 = g_ed[i + 1]; c2 = g_ed[i + 2]; c3 = g_ed[i + 3];
    }
    while (i + 4 <= end) {
        int nx = i + 4;
        bool hn = (nx + 4 <= end);
        uint2 n0, n1, n2, n3;
        if (hn) {
            n0 = g_ed[nx]; n1 = g_ed[nx + 1]; n2 = g_ed[nx + 2]; n3 = g_ed[nx + 3];
        }
        float f0 = __uint_as_float(c0.y) * fc[c0.x >> 20];
        float f1 = __uint_as_float(c1.y) * fc[c1.x >> 20];
        float f2 = __uint_as_float(c2.y) * fc[c2.x >> 20];
        float f3 = __uint_as_float(c3.y) * fc[c3.x >> 20];
        gfma(Hin, c0.x, f0, off4, ax, ay, az, aw);
        gfma(Hin, c1.x, f1, off4, ax, ay, az, aw);
        gfma(Hin, c2.x, f2, off4, ax, ay, az, aw);
        gfma(Hin, c3.x, f3, off4, ax, ay, az, aw);
        if (hn) { c0 = n0; c1 = n1; c2 = n2; c3 = n3; }
        i = nx;
    }
    for (; i < end; i++) {
        uint2 e0 = g_ed[i];
        float f0 = __uint_as_float(e0.y) * fc[e0.x >> 20];
        gfma(Hin, e0.x, f0, off4, ax, ay, az, aw);
    }

    __half2 o0 = __floats2half2_rn(ax, ay);
    __half2 o1 = __floats2half2_rn(az, aw);
    uint2 ov;
    ov.x = *(unsigned*)&o0;
    ov.y = *(unsigned*)&o1;
    *(uint2*)(Hout + (size_t)wid * CD + off4) = ov;
}

// ---------------- fused tail at target nodes (fp16 Xh + fp16 H1 mix) ---------
#define TGT 8
__global__ void __launch_bounds__(128) k_tail(const int* __restrict__ targets,
                                              const float* __restrict__ lin1_w,
                                              const float* __restrict__ lin1_b,
                                              const float* __restrict__ lin_w,
                                              const float* __restrict__ lin_b,
                                              float* __restrict__ out) {
    __shared__ float hc[TGT][CD];
    __shared__ float hs[TGT][DD];
    __shared__ int   tg[TGT];
    int tid = threadIdx.x;
    int m0 = blockIdx.x * TGT;
    if (tid < TGT) tg[tid] = targets[m0 + tid];
    __syncthreads();

    for (int idx = tid; idx < TGT * CD; idx += 128) {
        int t = idx >> 7, k = idx & 127;
        size_t p = (size_t)tg[t] * CD + k;
        float v = 0.5f * __half2float(g_Xh[p]) + 0.5f * __half2float(g_H1[p]);
        hc[t][k] = v > 0.f ? v : 0.f;
    }
    __syncthreads();

    int half_ = tid >> 6;
    int d = tid & 63;
    int t0 = half_ * 4;
    float a0 = lin1_b[d], a1 = a0, a2 = a0, a3 = a0;
    for (int k = 0; k < CD; k++) {
        float w = lin1_w[k * DD + d];
        a0 += hc[t0 + 0][k] * w;
        a1 += hc[t0 + 1][k] * w;
        a2 += hc[t0 + 2][k] * w;
        a3 += hc[t0 + 3][k] * w;
    }
    hs[t0 + 0][d] = a0;
    hs[t0 + 1][d] = a1;
    hs[t0 + 2][d] = a2;
    hs[t0 + 3][d] = a3;
    __syncthreads();

    int t = tid >> 4, j = tid & 15;
    float o = lin_b[j];
    for (int dd = 0; dd < DD; dd++)
        o += hs[t][dd] * lin_w[dd * NCLS + j];
    out[(size_t)(m0 + t) * NCLS + j] = o;
}

// ---------------- launcher ---------------------------------------------------
extern "C" void kernel_launch(void* const* d_in, const int* in_sizes, int n_in,
                              void* d_out, int out_size) {
    const float* X      = (const float*)d_in[0];
    const float* ev     = (const float*)d_in[1];
    const float* cw     = (const float*)d_in[2];
    const float* Ws     = (const float*)d_in[3];
    const float* lin1_w = (const float*)d_in[4];
    const float* lin1_b = (const float*)d_in[5];
    const float* lin_w  = (const float*)d_in[6];
    const float* lin_b  = (const float*)d_in[7];
    const int*   ei     = (const int*)d_in[8];
    const int*   tgt    = (const int*)d_in[9];
    float* out          = (float*)d_out;

    k_zero<<<(NN + 255) / 256, 256>>>(cw);
    k_hist<<<(TE + 255) / 256, 256>>>(ei);
    k_scan1<<<SNB, SCHUNK>>>();
    // gemm 4th so the ncu window captures it (independent of the scan chain)
    k_gemm<<<(NN + RT - 1) / RT, 256>>>(X, Ws);
    k_scan23<<<SNB, SCHUNK>>>();
    k_scatter<<<(TE + 255) / 256, 256>>>(ei, ev);

    k_spmm<<<(NN * 32 + 255) / 256, 256>>>(0);
    k_spmm<<<(NN * 32 + 255) / 256, 256>>>(1);

    k_tail<<<MM / TGT, 128>>>(tgt, lin1_w, lin1_b, lin_w, lin_b, out);
}

// round 15
// speedup vs baseline: 1.1674x; 1.1674x over previous
#include <cuda_runtime.h>
#include <cuda_fp16.h>
#include <cstdint>

#define NN      100000
#define TT      4
#define EE      400000
#define TE      1600000
#define CC      2
#define LL      2
#define WIN     128
#define DD      64
#define CD      128
#define NCLS    16
#define MM      10000

// ---------------- device scratch (static; no runtime allocation) ------------
__device__ __half   g_Xh[NN * CD];      // fp16 projected input (SpMM l0 in + tail mix)
__device__ __half   g_H0[NN * CD];      // fp16 layer-0 output
__device__ __half   g_H1[NN * CD];      // fp16 layer-1 output
__device__ uint2    g_ed[TE];           // packed edge: {col | type<<20, w bits}
__device__ int      g_rank[TE];         // within-destination rank (from hist)
__device__ int      g_cnt[NN];
__device__ int      g_off[NN + 1];
__device__ int      g_bsum[256];
__device__ float    g_filt[LL * CC * TT];

__device__ __forceinline__ unsigned tf32cvt(float x) {
    unsigned r;
    asm("cvt.rna.tf32.f32 %0, %1;" : "=r"(r) : "f"(x));
    return r;
}

// ---------------- zero counters + softmax over edge types (fused) -----------
__global__ void k_zero(const float* __restrict__ cw) {
    int i = blockIdx.x * blockDim.x + threadIdx.x;
    if (i < NN) g_cnt[i] = 0;
    if (blockIdx.x == 0 && threadIdx.x < LL * CC) {
        const float* p = cw + threadIdx.x * TT;
        float m = p[0];
        for (int t = 1; t < TT; t++) m = fmaxf(m, p[t]);
        float e[TT]; float s = 0.f;
        for (int t = 0; t < TT; t++) { e[t] = __expf(p[t] - m); s += e[t]; }
        float inv = 1.f / s;
        for (int t = 0; t < TT; t++) g_filt[threadIdx.x * TT + t] = e[t] * inv;
    }
}

// ---- hist: 2 edges/thread; rank recorded so scatter needs no atomic --------
__global__ void k_hist(const int* __restrict__ ei) {
    int p = blockIdx.x * blockDim.x + threadIdx.x;   // pair index
    if (p >= TE / 2) return;
    int idx = p * 2;
    int t = idx / EE;
    int e = idx - t * EE;                            // even; pair within one type row
    int2 d2 = *(const int2*)&ei[t * 2 * EE + e];
    int r0 = atomicAdd(&g_cnt[d2.x], 1);
    int r1 = atomicAdd(&g_cnt[d2.y], 1);
    *(int2*)&g_rank[idx] = make_int2(r0, r1);
}

#define SCHUNK 512
#define SNB    196            // ceil(100000/512)

__global__ void k_scan1() {
    __shared__ int s[SCHUNK];
    int tid = threadIdx.x;
    int i = blockIdx.x * SCHUNK + tid;
    int v = (i < NN) ? g_cnt[i] : 0;
    s[tid] = v;
    __syncthreads();
    for (int o = 1; o < SCHUNK; o <<= 1) {
        int t = (tid >= o) ? s[tid - o] : 0;
        __syncthreads();
        s[tid] += t;
        __syncthreads();
    }
    if (i < NN) g_off[i] = s[tid] - v;
    if (tid == SCHUNK - 1) g_bsum[blockIdx.x] = s[tid];
}

// fused: every block redundantly scans the 196 block sums, then applies base
__global__ void k_scan23() {
    __shared__ int s[256];
    int tid = threadIdx.x;
    if (tid < 256) s[tid] = (tid < SNB) ? g_bsum[tid] : 0;
    __syncthreads();
    for (int o = 1; o < 256; o <<= 1) {
        int t = 0;
        if (tid < 256 && tid >= o) t = s[tid - o];
        __syncthreads();
        if (tid < 256) s[tid] += t;
        __syncthreads();
    }
    int base = (blockIdx.x > 0) ? s[blockIdx.x - 1] : 0;
    int i = blockIdx.x * SCHUNK + tid;
    if (i < NN) g_off[i] = g_off[i] + base;
    if (blockIdx.x == 0 && tid == 0) g_off[NN] = TE;
}

// ---- scatter: 2 edges/thread, atomic-free (pos = off[dst] + rank) ----------
__global__ void k_scatter(const int* __restrict__ ei, const float* __restrict__ ev) {
    int p = blockIdx.x * blockDim.x + threadIdx.x;
    if (p >= TE / 2) return;
    int idx = p * 2;
    int t = idx / EE;
    int e = idx - t * EE;
    int2   d2 = *(const int2*)&ei[t * 2 * EE + e];
    int2   c2 = *(const int2*)&ei[t * 2 * EE + EE + e];
    float2 v2 = *(const float2*)&ev[idx];
    int2   r2 = *(const int2*)&g_rank[idx];
    uint2 rec0, rec1;
    rec0.x = (unsigned)c2.x | ((unsigned)t << 20);
    rec0.y = __float_as_uint(v2.x);
    rec1.x = (unsigned)c2.y | ((unsigned)t << 20);
    rec1.y = __float_as_uint(v2.y);
    g_ed[g_off[d2.x] + r2.x] = rec0;
    g_ed[g_off[d2.y] + r2.y] = rec1;
}

// ---------------- input projection: tf32 mma.sync (R13, measured 37us) ------
#define RT   64               // rows per block
#define KC   32               // k-chunk
#define XP   36               // padded k stride (bank-conflict-free fragments)

__global__ void __launch_bounds__(256) k_gemm(const float* __restrict__ X,
                                              const float* __restrict__ Ws) {
    __shared__ unsigned Xs[RT][XP];     // [row][k] tf32 bits
    __shared__ unsigned Wsm[CD][XP];    // [n][k] tf32 bits
    int tid  = threadIdx.x;
    int lane = tid & 31;
    int warp = tid >> 5;
    int mg   = warp >> 2;               // m-group 0..1
    int ng   = warp & 3;                // n-group 0..3
    int n0   = blockIdx.x * RT;
    int g  = lane >> 2;                 // group id 0..7
    int tg = lane & 3;                  // thread-in-group 0..3

    float acc[2][4][4];                 // [mtile][ntile][c0..c3]
#pragma unroll
    for (int mt = 0; mt < 2; mt++)
#pragma unroll
        for (int nt = 0; nt < 4; nt++)
#pragma unroll
            for (int r = 0; r < 4; r++) acc[mt][nt][r] = 0.f;

    for (int k0 = 0; k0 < WIN; k0 += KC) {
        // stage X chunk [RT x KC] (512 float4, 256 threads -> 2 each)
#pragma unroll
        for (int idx = tid; idx < RT * (KC / 4); idx += 256) {
            int row = idx >> 3;          // 8 float4 per row
            int c4  = (idx & 7) * 4;
            float4 v = make_float4(0.f, 0.f, 0.f, 0.f);
            if (n0 + row < NN)
                v = *(const float4*)&X[(size_t)(n0 + row) * WIN + k0 + c4];
            Xs[row][c4 + 0] = tf32cvt(v.x);
            Xs[row][c4 + 1] = tf32cvt(v.y);
            Xs[row][c4 + 2] = tf32cvt(v.z);
            Xs[row][c4 + 3] = tf32cvt(v.w);
        }
        // stage W chunk: thread handles n = tid&127, k half kh = tid>>7
        {
            int n  = tid & 127;
            int kh = tid >> 7;           // 0 or 1
            int c = n >> 6, d = n & 63;
            const float* wp = Ws + (size_t)c * WIN * DD
                                 + (size_t)(k0 + kh * 16) * DD + d;
#pragma unroll
            for (int k = 0; k < 16; k++)
                Wsm[n][kh * 16 + k] = tf32cvt(wp[(size_t)k * DD]);
        }
        __syncthreads();

#pragma unroll
        for (int ks = 0; ks < KC / 8; ks++) {
            int kb = ks * 8;
            unsigned a[2][4];
#pragma unroll
            for (int mt = 0; mt < 2; mt++) {
                int r = mg * 32 + mt * 16;
                a[mt][0] = Xs[r + g][kb + tg];
                a[mt][1] = Xs[r + g + 8][kb + tg];
                a[mt][2] = Xs[r + g][kb + tg + 4];
                a[mt][3] = Xs[r + g + 8][kb + tg + 4];
            }
#pragma unroll
            for (int nt = 0; nt < 4; nt++) {
                int n = ng * 32 + nt * 8 + g;
                unsigned b0 = Wsm[n][kb + tg];
                unsigned b1 = Wsm[n][kb + tg + 4];
#pragma unroll
                for (int mt = 0; mt < 2; mt++) {
                    asm volatile(
                        "mma.sync.aligned.m16n8k8.row.col.f32.tf32.tf32.f32 "
                        "{%0,%1,%2,%3}, {%4,%5,%6,%7}, {%8,%9}, {%0,%1,%2,%3};\n"
                        : "+f"(acc[mt][nt][0]), "+f"(acc[mt][nt][1]),
                          "+f"(acc[mt][nt][2]), "+f"(acc[mt][nt][3])
                        : "r"(a[mt][0]), "r"(a[mt][1]), "r"(a[mt][2]), "r"(a[mt][3]),
                          "r"(b0), "r"(b1));
                }
            }
        }
        __syncthreads();
    }

    // epilogue: fp16 only
#pragma unroll
    for (int mt = 0; mt < 2; mt++) {
        int r0 = n0 + mg * 32 + mt * 16 + g;
        int r1 = r0 + 8;
#pragma unroll
        for (int nt = 0; nt < 4; nt++) {
            int col = ng * 32 + nt * 8 + 2 * tg;
            if (r0 < NN)
                *(__half2*)&g_Xh[(size_t)r0 * CD + col] =
                    __floats2half2_rn(acc[mt][nt][0], acc[mt][nt][1]);
            if (r1 < NN)
                *(__half2*)&g_Xh[(size_t)r1 * CD + col] =
                    __floats2half2_rn(acc[mt][nt][2], acc[mt][nt][3]);
        }
    }
}

// ---------------- SpMM: warp per destination (R13-measured form) ------------
__device__ __forceinline__ void gfma(const __half* __restrict__ Hin, unsigned pc,
                                     float f, int off4,
                                     float& ax, float& ay, float& az, float& aw) {
    const uint2 hv = *(const uint2*)(Hin + (size_t)(pc & 0xFFFFFu) * CD + off4);
    float2 p0 = __half22float2(*(const __half2*)&hv.x);
    float2 p1 = __half22float2(*(const __half2*)&hv.y);
    ax += f * p0.x; ay += f * p0.y; az += f * p1.x; aw += f * p1.y;
}

__global__ void __launch_bounds__(256) k_spmm(int layer) {
    const __half* __restrict__ Hin  = (layer == 0) ? g_Xh : g_H0;
    __half* __restrict__       Hout = (layer == 0) ? g_H0 : g_H1;

    __shared__ float fs[CC * TT];
    int tid = threadIdx.x;
    if (tid < CC * TT) fs[tid] = g_filt[layer * CC * TT + tid];
    __syncthreads();

    int wid = (blockIdx.x * blockDim.x + tid) >> 5;
    if (wid >= NN) return;
    int lane = tid & 31;
    int c = lane >> 4;
    const float* fc = fs + c * TT;
    int off4 = lane * 4;

    int i   = g_off[wid];
    int end = g_off[wid + 1];
    float ax = 0.f, ay = 0.f, az = 0.f, aw = 0.f;

    for (; i + 4 <= end; i += 4) {
        uint2 e0 = g_ed[i], e1 = g_ed[i + 1], e2 = g_ed[i + 2], e3 = g_ed[i + 3];
        float f0 = __uint_as_float(e0.y) * fc[e0.x >> 20];
        float f1 = __uint_as_float(e1.y) * fc[e1.x >> 20];
        float f2 = __uint_as_float(e2.y) * fc[e2.x >> 20];
        float f3 = __uint_as_float(e3.y) * fc[e3.x >> 20];
        gfma(Hin, e0.x, f0, off4, ax, ay, az, aw);
        gfma(Hin, e1.x, f1, off4, ax, ay, az, aw);
        gfma(Hin, e2.x, f2, off4, ax, ay, az, aw);
        gfma(Hin, e3.x, f3, off4, ax, ay, az, aw);
    }
    for (; i < end; i++) {
        uint2 e0 = g_ed[i];
        float f0 = __uint_as_float(e0.y) * fc[e0.x >> 20];
        gfma(Hin, e0.x, f0, off4, ax, ay, az, aw);
    }

    __half2 o0 = __floats2half2_rn(ax, ay);
    __half2 o1 = __floats2half2_rn(az, aw);
    uint2 ov;
    ov.x = *(unsigned*)&o0;
    ov.y = *(unsigned*)&o1;
    *(uint2*)(Hout + (size_t)wid * CD + off4) = ov;
}

// ---------------- fused tail at target nodes (fp16 Xh + fp16 H1 mix) ---------
#define TGT 8
__global__ void __launch_bounds__(128) k_tail(const int* __restrict__ targets,
                                              const float* __restrict__ lin1_w,
                                              const float* __restrict__ lin1_b,
                                              const float* __restrict__ lin_w,
                                              const float* __restrict__ lin_b,
                                              float* __restrict__ out) {
    __shared__ float hc[TGT][CD];
    __shared__ float hs[TGT][DD];
    __shared__ int   tg[TGT];
    int tid = threadIdx.x;
    int m0 = blockIdx.x * TGT;
    if (tid < TGT) tg[tid] = targets[m0 + tid];
    __syncthreads();

    for (int idx = tid; idx < TGT * CD; idx += 128) {
        int t = idx >> 7, k = idx & 127;
        size_t p = (size_t)tg[t] * CD + k;
        float v = 0.5f * __half2float(g_Xh[p]) + 0.5f * __half2float(g_H1[p]);
        hc[t][k] = v > 0.f ? v : 0.f;
    }
    __syncthreads();

    int half_ = tid >> 6;
    int d = tid & 63;
    int t0 = half_ * 4;
    float a0 = lin1_b[d], a1 = a0, a2 = a0, a3 = a0;
    for (int k = 0; k < CD; k++) {
        float w = lin1_w[k * DD + d];
        a0 += hc[t0 + 0][k] * w;
        a1 += hc[t0 + 1][k] * w;
        a2 += hc[t0 + 2][k] * w;
        a3 += hc[t0 + 3][k] * w;
    }
    hs[t0 + 0][d] = a0;
    hs[t0 + 1][d] = a1;
    hs[t0 + 2][d] = a2;
    hs[t0 + 3][d] = a3;
    __syncthreads();

    int t = tid >> 4, j = tid & 15;
    float o = lin_b[j];
    for (int dd = 0; dd < DD; dd++)
        o += hs[t][dd] * lin_w[dd * NCLS + j];
    out[(size_t)(m0 + t) * NCLS + j] = o;
}

// ---------------- launcher ---------------------------------------------------
extern "C" void kernel_launch(void* const* d_in, const int* in_sizes, int n_in,
                              void* d_out, int out_size) {
    const float* X      = (const float*)d_in[0];
    const float* ev     = (const float*)d_in[1];
    const float* cw     = (const float*)d_in[2];
    const float* Ws     = (const float*)d_in[3];
    const float* lin1_w = (const float*)d_in[4];
    const float* lin1_b = (const float*)d_in[5];
    const float* lin_w  = (const float*)d_in[6];
    const float* lin_b  = (const float*)d_in[7];
    const int*   ei     = (const int*)d_in[8];
    const int*   tgt    = (const int*)d_in[9];
    float* out          = (float*)d_out;

    k_zero<<<(NN + 255) / 256, 256>>>(cw);
    k_hist<<<(TE / 2 + 255) / 256, 256>>>(ei);
    k_scan1<<<SNB, SCHUNK>>>();
    // gemm 4th so the ncu window captures it (independent of the scan chain)
    k_gemm<<<(NN + RT - 1) / RT, 256>>>(X, Ws);
    k_scan23<<<SNB, SCHUNK>>>();
    k_scatter<<<(TE / 2 + 255) / 256, 256>>>(ei, ev);

    k_spmm<<<(NN * 32 + 255) / 256, 256>>>(0);
    k_spmm<<<(NN * 32 + 255) / 256, 256>>>(1);

    k_tail<<<MM / TGT, 128>>>(tgt, lin1_w, lin1_b, lin_w, lin_b, out);
}

// round 16
// speedup vs baseline: 1.2328x; 1.0561x over previous
#include <cuda_runtime.h>
#include <cuda_fp16.h>
#include <cstdint>

#define NN      100000
#define TT      4
#define EE      400000
#define TE      1600000
#define CC      2
#define LL      2
#define WIN     128
#define DD      64
#define CD      128
#define NCLS    16
#define MM      10000

// ---------------- device scratch (static; no runtime allocation) ------------
__device__ __half   g_Xh[NN * CD];      // fp16 projected input (SpMM l0 in + tail mix)
__device__ __half   g_H0[NN * CD];      // fp16 layer-0 output
__device__ __half   g_H1[NN * CD];      // fp16 layer-1 output
__device__ uint2    g_ed[TE];           // packed edge: {col | type<<20, w bits}
__device__ int      g_rank[TE];         // within-destination rank (from hist)
__device__ int      g_cnt[NN];
__device__ int      g_off[NN + 1];
__device__ int      g_bsum[256];
__device__ float    g_filt[LL * CC * TT];

__device__ __forceinline__ unsigned tf32cvt(float x) {
    unsigned r;
    asm("cvt.rna.tf32.f32 %0, %1;" : "=r"(r) : "f"(x));
    return r;
}

// ---------------- zero counters + softmax over edge types (fused) -----------
__global__ void k_zero(const float* __restrict__ cw) {
    int i = blockIdx.x * blockDim.x + threadIdx.x;
    if (i < NN) g_cnt[i] = 0;
    if (blockIdx.x == 0 && threadIdx.x < LL * CC) {
        const float* p = cw + threadIdx.x * TT;
        float m = p[0];
        for (int t = 1; t < TT; t++) m = fmaxf(m, p[t]);
        float e[TT]; float s = 0.f;
        for (int t = 0; t < TT; t++) { e[t] = __expf(p[t] - m); s += e[t]; }
        float inv = 1.f / s;
        for (int t = 0; t < TT; t++) g_filt[threadIdx.x * TT + t] = e[t] * inv;
    }
}

// ---- hist: 2 edges/thread; rank recorded so scatter needs no atomic --------
__global__ void k_hist(const int* __restrict__ ei) {
    int p = blockIdx.x * blockDim.x + threadIdx.x;   // pair index
    if (p >= TE / 2) return;
    int idx = p * 2;
    int t = idx / EE;
    int e = idx - t * EE;                            // even; pair within one type row
    int2 d2 = *(const int2*)&ei[t * 2 * EE + e];
    int r0 = atomicAdd(&g_cnt[d2.x], 1);
    int r1 = atomicAdd(&g_cnt[d2.y], 1);
    *(int2*)&g_rank[idx] = make_int2(r0, r1);
}

#define SCHUNK 512
#define SNB    196            // ceil(100000/512)

__global__ void k_scan1() {
    __shared__ int s[SCHUNK];
    int tid = threadIdx.x;
    int i = blockIdx.x * SCHUNK + tid;
    int v = (i < NN) ? g_cnt[i] : 0;
    s[tid] = v;
    __syncthreads();
    for (int o = 1; o < SCHUNK; o <<= 1) {
        int t = (tid >= o) ? s[tid - o] : 0;
        __syncthreads();
        s[tid] += t;
        __syncthreads();
    }
    if (i < NN) g_off[i] = s[tid] - v;
    if (tid == SCHUNK - 1) g_bsum[blockIdx.x] = s[tid];
}

// fused: every block redundantly scans the 196 block sums, then applies base
__global__ void k_scan23() {
    __shared__ int s[256];
    int tid = threadIdx.x;
    if (tid < 256) s[tid] = (tid < SNB) ? g_bsum[tid] : 0;
    __syncthreads();
    for (int o = 1; o < 256; o <<= 1) {
        int t = 0;
        if (tid < 256 && tid >= o) t = s[tid - o];
        __syncthreads();
        if (tid < 256) s[tid] += t;
        __syncthreads();
    }
    int base = (blockIdx.x > 0) ? s[blockIdx.x - 1] : 0;
    int i = blockIdx.x * SCHUNK + tid;
    if (i < NN) g_off[i] = g_off[i] + base;
    if (blockIdx.x == 0 && tid == 0) g_off[NN] = TE;
}

// ---- scatter: 2 edges/thread, atomic-free (pos = off[dst] + rank) ----------
__global__ void k_scatter(const int* __restrict__ ei, const float* __restrict__ ev) {
    int p = blockIdx.x * blockDim.x + threadIdx.x;
    if (p >= TE / 2) return;
    int idx = p * 2;
    int t = idx / EE;
    int e = idx - t * EE;
    int2   d2 = *(const int2*)&ei[t * 2 * EE + e];
    int2   c2 = *(const int2*)&ei[t * 2 * EE + EE + e];
    float2 v2 = *(const float2*)&ev[idx];
    int2   r2 = *(const int2*)&g_rank[idx];
    uint2 rec0, rec1;
    rec0.x = (unsigned)c2.x | ((unsigned)t << 20);
    rec0.y = __float_as_uint(v2.x);
    rec1.x = (unsigned)c2.y | ((unsigned)t << 20);
    rec1.y = __float_as_uint(v2.y);
    g_ed[g_off[d2.x] + r2.x] = rec0;
    g_ed[g_off[d2.y] + r2.y] = rec1;
}

// ---------------- input projection: tf32 mma.sync (R13, measured ~37us) -----
#define RT   64               // rows per block
#define KC   32               // k-chunk
#define XP   36               // padded k stride (bank-conflict-free fragments)

__global__ void __launch_bounds__(256) k_gemm(const float* __restrict__ X,
                                              const float* __restrict__ Ws) {
    __shared__ unsigned Xs[RT][XP];     // [row][k] tf32 bits
    __shared__ unsigned Wsm[CD][XP];    // [n][k] tf32 bits
    int tid  = threadIdx.x;
    int lane = tid & 31;
    int warp = tid >> 5;
    int mg   = warp >> 2;               // m-group 0..1
    int ng   = warp & 3;                // n-group 0..3
    int n0   = blockIdx.x * RT;
    int g  = lane >> 2;                 // group id 0..7
    int tg = lane & 3;                  // thread-in-group 0..3

    float acc[2][4][4];                 // [mtile][ntile][c0..c3]
#pragma unroll
    for (int mt = 0; mt < 2; mt++)
#pragma unroll
        for (int nt = 0; nt < 4; nt++)
#pragma unroll
            for (int r = 0; r < 4; r++) acc[mt][nt][r] = 0.f;

    for (int k0 = 0; k0 < WIN; k0 += KC) {
        // stage X chunk [RT x KC] (512 float4, 256 threads -> 2 each)
#pragma unroll
        for (int idx = tid; idx < RT * (KC / 4); idx += 256) {
            int row = idx >> 3;          // 8 float4 per row
            int c4  = (idx & 7) * 4;
            float4 v = make_float4(0.f, 0.f, 0.f, 0.f);
            if (n0 + row < NN)
                v = *(const float4*)&X[(size_t)(n0 + row) * WIN + k0 + c4];
            Xs[row][c4 + 0] = tf32cvt(v.x);
            Xs[row][c4 + 1] = tf32cvt(v.y);
            Xs[row][c4 + 2] = tf32cvt(v.z);
            Xs[row][c4 + 3] = tf32cvt(v.w);
        }
        // stage W chunk: thread handles n = tid&127, k half kh = tid>>7
        {
            int n  = tid & 127;
            int kh = tid >> 7;           // 0 or 1
            int c = n >> 6, d = n & 63;
            const float* wp = Ws + (size_t)c * WIN * DD
                                 + (size_t)(k0 + kh * 16) * DD + d;
#pragma unroll
            for (int k = 0; k < 16; k++)
                Wsm[n][kh * 16 + k] = tf32cvt(wp[(size_t)k * DD]);
        }
        __syncthreads();

#pragma unroll
        for (int ks = 0; ks < KC / 8; ks++) {
            int kb = ks * 8;
            unsigned a[2][4];
#pragma unroll
            for (int mt = 0; mt < 2; mt++) {
                int r = mg * 32 + mt * 16;
                a[mt][0] = Xs[r + g][kb + tg];
                a[mt][1] = Xs[r + g + 8][kb + tg];
                a[mt][2] = Xs[r + g][kb + tg + 4];
                a[mt][3] = Xs[r + g + 8][kb + tg + 4];
            }
#pragma unroll
            for (int nt = 0; nt < 4; nt++) {
                int n = ng * 32 + nt * 8 + g;
                unsigned b0 = Wsm[n][kb + tg];
                unsigned b1 = Wsm[n][kb + tg + 4];
#pragma unroll
                for (int mt = 0; mt < 2; mt++) {
                    asm volatile(
                        "mma.sync.aligned.m16n8k8.row.col.f32.tf32.tf32.f32 "
                        "{%0,%1,%2,%3}, {%4,%5,%6,%7}, {%8,%9}, {%0,%1,%2,%3};\n"
                        : "+f"(acc[mt][nt][0]), "+f"(acc[mt][nt][1]),
                          "+f"(acc[mt][nt][2]), "+f"(acc[mt][nt][3])
                        : "r"(a[mt][0]), "r"(a[mt][1]), "r"(a[mt][2]), "r"(a[mt][3]),
                          "r"(b0), "r"(b1));
                }
            }
        }
        __syncthreads();
    }

    // epilogue: fp16 only
#pragma unroll
    for (int mt = 0; mt < 2; mt++) {
        int r0 = n0 + mg * 32 + mt * 16 + g;
        int r1 = r0 + 8;
#pragma unroll
        for (int nt = 0; nt < 4; nt++) {
            int col = ng * 32 + nt * 8 + 2 * tg;
            if (r0 < NN)
                *(__half2*)&g_Xh[(size_t)r0 * CD + col] =
                    __floats2half2_rn(acc[mt][nt][0], acc[mt][nt][1]);
            if (r1 < NN)
                *(__half2*)&g_Xh[(size_t)r1 * CD + col] =
                    __floats2half2_rn(acc[mt][nt][2], acc[mt][nt][3]);
        }
    }
}

// ---------------- SpMM: warp per destination (R13-measured form) ------------
__device__ __forceinline__ void gfma(const __half* __restrict__ Hin, unsigned pc,
                                     float f, int off4,
                                     float& ax, float& ay, float& az, float& aw) {
    const uint2 hv = *(const uint2*)(Hin + (size_t)(pc & 0xFFFFFu) * CD + off4);
    float2 p0 = __half22float2(*(const __half2*)&hv.x);
    float2 p1 = __half22float2(*(const __half2*)&hv.y);
    ax += f * p0.x; ay += f * p0.y; az += f * p1.x; aw += f * p1.y;
}

__global__ void __launch_bounds__(256) k_spmm(int layer) {
    const __half* __restrict__ Hin  = (layer == 0) ? g_Xh : g_H0;
    __half* __restrict__       Hout = (layer == 0) ? g_H0 : g_H1;

    __shared__ float fs[CC * TT];
    int tid = threadIdx.x;
    if (tid < CC * TT) fs[tid] = g_filt[layer * CC * TT + tid];
    __syncthreads();

    int wid = (blockIdx.x * blockDim.x + tid) >> 5;
    if (wid >= NN) return;
    int lane = tid & 31;
    int c = lane >> 4;
    const float* fc = fs + c * TT;
    int off4 = lane * 4;

    int i   = g_off[wid];
    int end = g_off[wid + 1];
    float ax = 0.f, ay = 0.f, az = 0.f, aw = 0.f;

    for (; i + 4 <= end; i += 4) {
        uint2 e0 = g_ed[i], e1 = g_ed[i + 1], e2 = g_ed[i + 2], e3 = g_ed[i + 3];
        float f0 = __uint_as_float(e0.y) * fc[e0.x >> 20];
        float f1 = __uint_as_float(e1.y) * fc[e1.x >> 20];
        float f2 = __uint_as_float(e2.y) * fc[e2.x >> 20];
        float f3 = __uint_as_float(e3.y) * fc[e3.x >> 20];
        gfma(Hin, e0.x, f0, off4, ax, ay, az, aw);
        gfma(Hin, e1.x, f1, off4, ax, ay, az, aw);
        gfma(Hin, e2.x, f2, off4, ax, ay, az, aw);
        gfma(Hin, e3.x, f3, off4, ax, ay, az, aw);
    }
    for (; i < end; i++) {
        uint2 e0 = g_ed[i];
        float f0 = __uint_as_float(e0.y) * fc[e0.x >> 20];
        gfma(Hin, e0.x, f0, off4, ax, ay, az, aw);
    }

    __half2 o0 = __floats2half2_rn(ax, ay);
    __half2 o1 = __floats2half2_rn(az, aw);
    uint2 ov;
    ov.x = *(unsigned*)&o0;
    ov.y = *(unsigned*)&o1;
    *(uint2*)(Hout + (size_t)wid * CD + off4) = ov;
}

// ---------------- fused tail at target nodes (fp16 Xh + fp16 H1 mix) ---------
#define TGT 8
__global__ void __launch_bounds__(128) k_tail(const int* __restrict__ targets,
                                              const float* __restrict__ lin1_w,
                                              const float* __restrict__ lin1_b,
                                              const float* __restrict__ lin_w,
                                              const float* __restrict__ lin_b,
                                              float* __restrict__ out) {
    __shared__ float hc[TGT][CD];
    __shared__ float hs[TGT][DD];
    __shared__ int   tg[TGT];
    int tid = threadIdx.x;
    int m0 = blockIdx.x * TGT;
    if (tid < TGT) tg[tid] = targets[m0 + tid];
    __syncthreads();

    for (int idx = tid; idx < TGT * CD; idx += 128) {
        int t = idx >> 7, k = idx & 127;
        size_t p = (size_t)tg[t] * CD + k;
        float v = 0.5f * __half2float(g_Xh[p]) + 0.5f * __half2float(g_H1[p]);
        hc[t][k] = v > 0.f ? v : 0.f;
    }
    __syncthreads();

    int half_ = tid >> 6;
    int d = tid & 63;
    int t0 = half_ * 4;
    float a0 = lin1_b[d], a1 = a0, a2 = a0, a3 = a0;
    for (int k = 0; k < CD; k++) {
        float w = lin1_w[k * DD + d];
        a0 += hc[t0 + 0][k] * w;
        a1 += hc[t0 + 1][k] * w;
        a2 += hc[t0 + 2][k] * w;
        a3 += hc[t0 + 3][k] * w;
    }
    hs[t0 + 0][d] = a0;
    hs[t0 + 1][d] = a1;
    hs[t0 + 2][d] = a2;
    hs[t0 + 3][d] = a3;
    __syncthreads();

    int t = tid >> 4, j = tid & 15;
    float o = lin_b[j];
    for (int dd = 0; dd < DD; dd++)
        o += hs[t][dd] * lin_w[dd * NCLS + j];
    out[(size_t)(m0 + t) * NCLS + j] = o;
}

// ---------------- launcher: fork gemm onto a side stream ---------------------
extern "C" void kernel_launch(void* const* d_in, const int* in_sizes, int n_in,
                              void* d_out, int out_size) {
    const float* X      = (const float*)d_in[0];
    const float* ev     = (const float*)d_in[1];
    const float* cw     = (const float*)d_in[2];
    const float* Ws     = (const float*)d_in[3];
    const float* lin1_w = (const float*)d_in[4];
    const float* lin1_b = (const float*)d_in[5];
    const float* lin_w  = (const float*)d_in[6];
    const float* lin_b  = (const float*)d_in[7];
    const int*   ei     = (const int*)d_in[8];
    const int*   tgt    = (const int*)d_in[9];
    float* out          = (float*)d_out;

    // one-time host resources (no device memory allocation)
    static cudaStream_t s2 = nullptr;
    static cudaEvent_t  evFork = nullptr, evJoin = nullptr;
    if (s2 == nullptr) {
        cudaStreamCreateWithFlags(&s2, cudaStreamNonBlocking);
        cudaEventCreateWithFlags(&evFork, cudaEventDisableTiming);
        cudaEventCreateWithFlags(&evJoin, cudaEventDisableTiming);
    }

    // fork: gemm (independent of CSR chain) runs on s2
    cudaEventRecord(evFork, 0);
    cudaStreamWaitEvent(s2, evFork, 0);
    k_gemm<<<(NN + RT - 1) / RT, 256, 0, s2>>>(X, Ws);
    cudaEventRecord(evJoin, s2);

    // CSR chain on the main (capturing) stream
    k_zero<<<(NN + 255) / 256, 256>>>(cw);
    k_hist<<<(TE / 2 + 255) / 256, 256>>>(ei);
    k_scan1<<<SNB, SCHUNK>>>();
    k_scan23<<<SNB, SCHUNK>>>();
    k_scatter<<<(TE / 2 + 255) / 256, 256>>>(ei, ev);

    // join: spmm needs both g_Xh (gemm) and the CSR arrays
    cudaStreamWaitEvent(0, evJoin, 0);

    k_spmm<<<(NN * 32 + 255) / 256, 256>>>(0);
    k_spmm<<<(NN * 32 + 255) / 256, 256>>>(1);

    k_tail<<<MM / TGT, 128>>>(tgt, lin1_w, lin1_b, lin_w, lin_b, out);
}